// round 3
// baseline (speedup 1.0000x reference)
#include <cuda_runtime.h>
#include <math.h>

#define E_TOTAL 160000
#define NN 10000
#define TILE 64
#define NT 256
#define ASTR 333
#define EPS 1e-8f

// ---- dynamic smem layout (float offsets) ----
#define OFF_A     0                    // 64 x 333         = 21312
#define OFF_VP    21312                // 64 x 108 (v_pre) =  6912 ; reused: VO1 (3072) + VH2 (3072)
#define OFF_VO1   (OFF_VP)
#define OFF_VH2   (OFF_VP + 3072)
#define OFF_VH    28224                // 64 x 108 (v_hid1)=  6912
#define OFF_S2    35136                // 64 x 128 silu2   =  8192
#define OFF_BS    43328                // 32 x 128 B tile  =  4096  (16B aligned)
#define OFF_F     47424                // 64 x 9 frames    =   576
#define OFF_VF    48000                // 64 x 9 vframes   =   576
#define OFF_GATE  48576                // 64 x 16          =  1024
#define OFF_ATTN  49600                // 64
#define OFF_IDX   49664                // 128 ints (rows, cols)
#define OFF_W     49792
// weight sub-offsets within OFF_W
#define W_DOWN1 0
#define W_DF1   1296
#define W_UP1   1404
#define W_G1    1980
#define W_DOWN2 4028
#define W_DF2   4284
#define W_UP2   4332
#define W_G2    4588
#define W_ATT   6636
#define W_BSO1  6764
#define W_BSO2  6892
#define W_BG1   7020
#define W_BG2   7036
#define W_ATTB  7052
#define W_TOTAL 7053
#define SMEM_FLOATS (OFF_W + W_TOTAL)   // 56845 floats = 227380 B < 232448 B limit

// normalized edge indices (handles int32-vs-int64 metadata ambiguity)
__device__ int g_idx[2 * E_TOTAL];

__device__ __forceinline__ float sigm(float x) { return 1.0f / (1.0f + __expf(-x)); }
__device__ __forceinline__ float silu(float x) { return x * sigm(x); }

__device__ __forceinline__ void copyw(float* dst, const float* __restrict__ src, int n, int tid) {
    for (int i = tid; i < n; i += NT) dst[i] = src[i];
}

// Normalize edge_index to int32 regardless of source width.
// If the buffer is int64 (little-endian, values in [0,10000)), every odd
// int32 word of the first 64 is zero; random int32 indices make that
// essentially impossible (p ~ 1e-128). Deterministic.
__global__ void convert_idx_kernel(const int* __restrict__ raw) {
    int any = 0;
    #pragma unroll
    for (int i = 1; i < 64; i += 2) any |= raw[i];
    const bool is64 = (any == 0);
    int i = blockIdx.x * blockDim.x + threadIdx.x;
    if (i < 2 * E_TOTAL) g_idx[i] = is64 ? raw[2 * i] : raw[i];
}

// GEMM: C[4][8] += A_tile[64 x K] @ W[K x 128], A in smem (stride ASTR), W streamed via Bs
__device__ __forceinline__ void gemm_tile(const float* __restrict__ W, int K,
                                          const float* A, float* Bs,
                                          float C[4][8], int ty, int tx, int tid) {
    for (int k0 = 0; k0 < K; k0 += 32) {
        int kb = min(32, K - k0);
        {
            const float4* src = (const float4*)(W + (size_t)k0 * 128);
            float4* dst = (float4*)Bs;
            int nv = kb * 32;
            for (int i = tid; i < nv; i += NT) dst[i] = src[i];
        }
        __syncthreads();
        const float* Arow0 = A + (ty * 4 + 0) * ASTR + k0;
        const float* Arow1 = A + (ty * 4 + 1) * ASTR + k0;
        const float* Arow2 = A + (ty * 4 + 2) * ASTR + k0;
        const float* Arow3 = A + (ty * 4 + 3) * ASTR + k0;
        #pragma unroll 4
        for (int kk = 0; kk < kb; ++kk) {
            float a0 = Arow0[kk], a1 = Arow1[kk], a2 = Arow2[kk], a3 = Arow3[kk];
            float4 p0 = *(const float4*)(Bs + kk * 128 + tx * 8);
            float4 p1 = *(const float4*)(Bs + kk * 128 + tx * 8 + 4);
            float bb[8] = {p0.x, p0.y, p0.z, p0.w, p1.x, p1.y, p1.z, p1.w};
            #pragma unroll
            for (int j = 0; j < 8; ++j) {
                C[0][j] += a0 * bb[j];
                C[1][j] += a1 * bb[j];
                C[2][j] += a2 * bb[j];
                C[3][j] += a3 * bb[j];
            }
        }
        __syncthreads();
    }
}

extern __shared__ float sm[];

__global__ void __launch_bounds__(NT, 1) gcp_kernel(
    const float* __restrict__ node_s, const float* __restrict__ node_v,
    const float* __restrict__ edge_s, const float* __restrict__ edge_v,
    const float* __restrict__ frames,
    const float* __restrict__ g1Wdown, const float* __restrict__ g1Wdf,
    const float* __restrict__ g1Wso,   const float* __restrict__ g1bso,
    const float* __restrict__ g1Wup,   const float* __restrict__ g1Wg,
    const float* __restrict__ g1bg,
    const float* __restrict__ g2Wdown, const float* __restrict__ g2Wdf,
    const float* __restrict__ g2Wso,   const float* __restrict__ g2bso,
    const float* __restrict__ g2Wup,   const float* __restrict__ g2Wg,
    const float* __restrict__ g2bg,
    const float* __restrict__ attW, const float* __restrict__ attb,
    float* __restrict__ out)
{
    const int tid = threadIdx.x;
    const int e0 = blockIdx.x * TILE;
    const int ty = tid >> 4, tx = tid & 15;

    float* A    = sm + OFF_A;
    float* VP   = sm + OFF_VP;
    float* VO1  = sm + OFF_VO1;
    float* VH2  = sm + OFF_VH2;
    float* VH   = sm + OFF_VH;
    float* S2   = sm + OFF_S2;
    float* Bs   = sm + OFF_BS;
    float* F    = sm + OFF_F;
    float* VF   = sm + OFF_VF;
    float* GATE = sm + OFF_GATE;
    float* ATTN = sm + OFF_ATTN;
    int*   rows = (int*)(sm + OFF_IDX);
    int*   cols = rows + TILE;
    float* Ws   = sm + OFF_W;

    // ---- load small weights ----
    copyw(Ws + W_DOWN1, g1Wdown, 1296, tid);
    copyw(Ws + W_DF1,   g1Wdf,   108,  tid);
    copyw(Ws + W_UP1,   g1Wup,   576,  tid);
    copyw(Ws + W_G1,    g1Wg,    2048, tid);
    copyw(Ws + W_DOWN2, g2Wdown, 256,  tid);
    copyw(Ws + W_DF2,   g2Wdf,   48,   tid);
    copyw(Ws + W_UP2,   g2Wup,   256,  tid);
    copyw(Ws + W_G2,    g2Wg,    2048, tid);
    copyw(Ws + W_ATT,   attW,    128,  tid);
    copyw(Ws + W_BSO1,  g1bso,   128,  tid);
    copyw(Ws + W_BSO2,  g2bso,   128,  tid);
    copyw(Ws + W_BG1,   g1bg,    16,   tid);
    copyw(Ws + W_BG2,   g2bg,    16,   tid);
    if (tid == 0) Ws[W_ATTB] = attb[0];
    if (tid < TILE) {
        rows[tid] = g_idx[e0 + tid];
        cols[tid] = g_idx[E_TOTAL + e0 + tid];
    }
    __syncthreads();

    // ---- Phase 1: gather ms -> A[:,0:288], v_pre -> VP, frames -> F ----
    for (int idx = tid; idx < TILE * 288; idx += NT) {
        int e = idx / 288, k = idx - e * 288;
        float v;
        if (k < 128)      v = node_s[(size_t)rows[e] * 128 + k];
        else if (k < 160) v = edge_s[(size_t)(e0 + e) * 32 + (k - 128)];
        else              v = node_s[(size_t)cols[e] * 128 + (k - 160)];
        A[e * ASTR + k] = v;
    }
    for (int idx = tid; idx < TILE * 108; idx += NT) {
        int e = idx / 108, r = idx - e * 108;
        int i = r / 3, d = r - i * 3;
        float v;
        if (i < 16)      v = node_v[(size_t)rows[e] * 48 + i * 3 + d];
        else if (i < 20) v = edge_v[(size_t)(e0 + e) * 12 + (i - 16) * 3 + d];
        else             v = node_v[(size_t)cols[e] * 48 + (i - 20) * 3 + d];
        VP[e * 108 + r] = v;   // VP[e][i*3+d] == v_pre[d][i]
    }
    for (int idx = tid; idx < TILE * 9; idx += NT) {
        int e = idx / 9, r = idx - e * 9;
        F[e * 9 + r] = frames[(size_t)(e0 + e) * 9 + r];
    }
    __syncthreads();

    // ---- Phase 2: v_hid1 [e][d][h] , v_frames1 [e][d][j] ----
    for (int idx = tid; idx < TILE * 108; idx += NT) {
        int e = idx / 108, r = idx - e * 108;
        int d = r / 36, h = r - d * 36;
        float s = 0.f;
        #pragma unroll 4
        for (int i = 0; i < 36; ++i) s += VP[e * 108 + i * 3 + d] * Ws[W_DOWN1 + i * 36 + h];
        VH[e * 108 + d * 36 + h] = s;
    }
    for (int idx = tid; idx < TILE * 9; idx += NT) {
        int e = idx / 9, r = idx - e * 9;
        int d = r / 3, j = r - d * 3;
        float s = 0.f;
        #pragma unroll 4
        for (int i = 0; i < 36; ++i) s += VP[e * 108 + i * 3 + d] * Ws[W_DF1 + i * 3 + j];
        VF[e * 9 + d * 3 + j] = s;
    }
    __syncthreads();

    // ---- Phase 3: v_norm1 -> A[:,288:324], local1 -> A[:,324:333] ----
    for (int idx = tid; idx < TILE * 36; idx += NT) {
        int e = idx / 36, h = idx - e * 36;
        float a = VH[e * 108 + h], b = VH[e * 108 + 36 + h], c = VH[e * 108 + 72 + h];
        A[e * ASTR + 288 + h] = sqrtf(a * a + b * b + c * c + EPS);
    }
    for (int idx = tid; idx < TILE * 9; idx += NT) {
        int e = idx / 9, r = idx - e * 9;
        int j = r / 3, i = r - j * 3;
        float s = 0.f;
        #pragma unroll
        for (int k = 0; k < 3; ++k) s += F[e * 9 + i * 3 + k] * VF[e * 9 + k * 3 + j];
        A[e * ASTR + 324 + r] = s;   // local[j*3+i]
    }
    __syncthreads();

    // ---- Phase 4: GEMM1, epilogue silu -> A[:,0:128] ----
    {
        float C[4][8];
        #pragma unroll
        for (int i = 0; i < 4; ++i)
            #pragma unroll
            for (int j = 0; j < 8; ++j) C[i][j] = 0.f;
        gemm_tile(g1Wso, 333, A, Bs, C, ty, tx, tid);
        #pragma unroll
        for (int i = 0; i < 4; ++i) {
            int e = ty * 4 + i;
            #pragma unroll
            for (int j = 0; j < 8; ++j) {
                int o = tx * 8 + j;
                A[e * ASTR + o] = silu(C[i][j] + Ws[W_BSO1 + o]);
            }
        }
    }
    __syncthreads();

    // ---- Phase 5: gate1 = sigmoid(silu(s1) @ Wg1 + bg1) ----
    for (int idx = tid; idx < TILE * 16; idx += NT) {
        int e = idx / 16, o = idx - e * 16;
        float s = Ws[W_BG1 + o];
        #pragma unroll 4
        for (int j = 0; j < 128; ++j) s += A[e * ASTR + j] * Ws[W_G1 + j * 16 + o];
        GATE[e * 16 + o] = sigm(s);
    }
    __syncthreads();

    // ---- Phase 6: v_out1[e][o][d] = gate1 * (v_hid1 @ Wup1) -> VO1 (overwrites VP) ----
    for (int idx = tid; idx < TILE * 48; idx += NT) {
        int e = idx / 48, r = idx - e * 48;
        int o = r / 3, d = r - o * 3;
        float s = 0.f;
        #pragma unroll 4
        for (int h = 0; h < 36; ++h) s += VH[e * 108 + d * 36 + h] * Ws[W_UP1 + h * 16 + o];
        VO1[e * 48 + r] = GATE[e * 16 + o] * s;
    }
    __syncthreads();

    // ---- Phase 7: v_hid2, v_frames2 ----
    for (int idx = tid; idx < TILE * 48; idx += NT) {
        int e = idx / 48, r = idx - e * 48;
        int d = r / 16, h = r - d * 16;
        float s = 0.f;
        #pragma unroll
        for (int o = 0; o < 16; ++o) s += VO1[e * 48 + o * 3 + d] * Ws[W_DOWN2 + o * 16 + h];
        VH2[e * 48 + d * 16 + h] = s;
    }
    for (int idx = tid; idx < TILE * 9; idx += NT) {
        int e = idx / 9, r = idx - e * 9;
        int d = r / 3, j = r - d * 3;
        float s = 0.f;
        #pragma unroll
        for (int o = 0; o < 16; ++o) s += VO1[e * 48 + o * 3 + d] * Ws[W_DF2 + o * 3 + j];
        VF[e * 9 + d * 3 + j] = s;
    }
    __syncthreads();

    // ---- Phase 8: v_norm2 -> A[:,128:144], local2 -> A[:,144:153] ----
    for (int idx = tid; idx < TILE * 16; idx += NT) {
        int e = idx / 16, h = idx - e * 16;
        float a = VH2[e * 48 + h], b = VH2[e * 48 + 16 + h], c = VH2[e * 48 + 32 + h];
        A[e * ASTR + 128 + h] = sqrtf(a * a + b * b + c * c + EPS);
    }
    for (int idx = tid; idx < TILE * 9; idx += NT) {
        int e = idx / 9, r = idx - e * 9;
        int j = r / 3, i = r - j * 3;
        float s = 0.f;
        #pragma unroll
        for (int k = 0; k < 3; ++k) s += F[e * 9 + i * 3 + k] * VF[e * 9 + k * 3 + j];
        A[e * ASTR + 144 + r] = s;
    }
    __syncthreads();

    // ---- Phase 9: GEMM2 (K=153), epilogue silu -> S2 ----
    {
        float C[4][8];
        #pragma unroll
        for (int i = 0; i < 4; ++i)
            #pragma unroll
            for (int j = 0; j < 8; ++j) C[i][j] = 0.f;
        gemm_tile(g2Wso, 153, A, Bs, C, ty, tx, tid);
        #pragma unroll
        for (int i = 0; i < 4; ++i) {
            int e = ty * 4 + i;
            #pragma unroll
            for (int j = 0; j < 8; ++j) {
                int o = tx * 8 + j;
                S2[e * 128 + o] = silu(C[i][j] + Ws[W_BSO2 + o]);
            }
        }
    }
    __syncthreads();

    // ---- Phase 10: gate2 ----
    for (int idx = tid; idx < TILE * 16; idx += NT) {
        int e = idx / 16, o = idx - e * 16;
        float s = Ws[W_BG2 + o];
        #pragma unroll 4
        for (int j = 0; j < 128; ++j) s += S2[e * 128 + j] * Ws[W_G2 + j * 16 + o];
        GATE[e * 16 + o] = sigm(s);
    }
    __syncthreads();

    // ---- Phase 11: v_final (in-place VO1), s_final (in-place A[:,0:128]) ----
    for (int idx = tid; idx < TILE * 48; idx += NT) {
        int e = idx / 48, r = idx - e * 48;
        int o = r / 3, d = r - o * 3;
        float s = 0.f;
        #pragma unroll
        for (int h = 0; h < 16; ++h) s += VH2[e * 48 + d * 16 + h] * Ws[W_UP2 + h * 16 + o];
        VO1[e * 48 + r] += GATE[e * 16 + o] * s;
    }
    for (int idx = tid; idx < TILE * 128; idx += NT) {
        int e = idx >> 7, j = idx & 127;
        A[e * ASTR + j] += S2[e * 128 + j];
    }
    __syncthreads();

    // ---- Phase 12: attention scalar per edge (4 lanes/edge) ----
    {
        int e = tid >> 2, l = tid & 3;
        float p = 0.f;
        for (int j = l; j < 128; j += 4) p += A[e * ASTR + j] * Ws[W_ATT + j];
        p += __shfl_down_sync(0xffffffffu, p, 2);
        p += __shfl_down_sync(0xffffffffu, p, 1);
        if (l == 0) ATTN[e] = sigm(p + Ws[W_ATTB]);
    }
    __syncthreads();

    // ---- Phase 13: scatter-add to out[row] ----
    for (int idx = tid; idx < TILE * 128; idx += NT) {
        int e = idx >> 7, j = idx & 127;
        atomicAdd(&out[(size_t)rows[e] * 176 + j], A[e * ASTR + j] * ATTN[e]);
    }
    for (int idx = tid; idx < TILE * 48; idx += NT) {
        int e = idx / 48, r = idx - e * 48;
        atomicAdd(&out[(size_t)rows[e] * 176 + 128 + r], VO1[e * 48 + r]);
    }
}

__global__ void zero_kernel(float4* __restrict__ out, int n4) {
    int i = blockIdx.x * blockDim.x + threadIdx.x;
    if (i < n4) out[i] = make_float4(0.f, 0.f, 0.f, 0.f);
}

extern "C" void kernel_launch(void* const* d_in, const int* in_sizes, int n_in,
                              void* d_out, int out_size) {
    const float* node_s  = (const float*)d_in[0];
    const float* node_v  = (const float*)d_in[1];
    const float* edge_s  = (const float*)d_in[2];
    const float* edge_v  = (const float*)d_in[3];
    const float* frames  = (const float*)d_in[4];
    const float* g1Wdown = (const float*)d_in[5];
    const float* g1Wdf   = (const float*)d_in[6];
    const float* g1Wso   = (const float*)d_in[7];
    const float* g1bso   = (const float*)d_in[8];
    const float* g1Wup   = (const float*)d_in[9];
    const float* g1Wg    = (const float*)d_in[10];
    const float* g1bg    = (const float*)d_in[11];
    const float* g2Wdown = (const float*)d_in[12];
    const float* g2Wdf   = (const float*)d_in[13];
    const float* g2Wso   = (const float*)d_in[14];
    const float* g2bso   = (const float*)d_in[15];
    const float* g2Wup   = (const float*)d_in[16];
    const float* g2Wg    = (const float*)d_in[17];
    const float* g2bg    = (const float*)d_in[18];
    const float* attW    = (const float*)d_in[19];
    const float* attb    = (const float*)d_in[20];
    const int*   ei_raw  = (const int*)d_in[21];   // width detected on device
    float* out = (float*)d_out;

    size_t smem = SMEM_FLOATS * sizeof(float);
    cudaFuncSetAttribute(gcp_kernel, cudaFuncAttributeMaxDynamicSharedMemorySize, (int)smem);

    convert_idx_kernel<<<(2 * E_TOTAL + 255) / 256, 256>>>(ei_raw);

    int n4 = out_size / 4;
    zero_kernel<<<(n4 + 255) / 256, 256>>>((float4*)d_out, n4);

    gcp_kernel<<<E_TOTAL / TILE, NT, smem>>>(
        node_s, node_v, edge_s, edge_v, frames,
        g1Wdown, g1Wdf, g1Wso, g1bso, g1Wup, g1Wg, g1bg,
        g2Wdown, g2Wdf, g2Wso, g2bso, g2Wup, g2Wg, g2bg,
        attW, attb, out);
}